// round 1
// baseline (speedup 1.0000x reference)
#include <cuda_runtime.h>
#include <cuda_bf16.h>

// Problem constants
#define BB 3
#define HH 256
#define WW 256
#define CC 16
#define NB 4
#define COUT 64
#define SN 64          // SNx = SNy = 64 patches per dim
#define EPS 1e-3f

// Scratch (allocation-free rule: __device__ globals)
__device__ float g_x1[BB * HH * WW * COUT];     // conv1 output (relu'd)
__device__ float g_bf[BB * HH * WW * COUT];     // conv2 out -> softmax/mask in-place (b_features)
__device__ float g_ratio[BB * SN * SN * CC * NB];

// ---------------------------------------------------------------------------
// Direct 3x3 SAME conv + folded BN (+ optional ReLU).
// Block: 256 threads = 64 oc x 4 pixel-groups; tile = 64 x-contiguous pixels
// of one row, all 64 output channels. Input channels processed in chunks of 8
// staged in shared memory together with the weight chunk.
// Each thread: 1 oc, 16 pixels (register accumulators).
// ---------------------------------------------------------------------------
template <int CIN>
__global__ __launch_bounds__(256) void conv3x3_bn(
    const float* __restrict__ in, const float* __restrict__ wgt,
    const float* __restrict__ bias, const float* __restrict__ gam,
    const float* __restrict__ bet, const float* __restrict__ mu,
    const float* __restrict__ var, float* __restrict__ out, int do_relu)
{
    __shared__ __align__(16) float s_in[3][8][72];   // [ky][ic_local][4 + rel], rel in [-1,64]
    __shared__ float s_w[9][8][64];                  // [ky*3+kx][ic_local][oc]

    const int tid = threadIdx.x;
    const int oc  = tid & 63;
    const int grp = tid >> 6;          // 0..3
    const int px0 = grp * 16;          // pixel offset within tile

    const int xbase = blockIdx.x * 64;
    const int y     = blockIdx.y;
    const int bb    = blockIdx.z;

    float acc[16];
#pragma unroll
    for (int p = 0; p < 16; ++p) acc[p] = 0.f;

    for (int ic0 = 0; ic0 < CIN; ic0 += 8) {
        __syncthreads();
        // weights chunk: 9 * 8 * 64 = 4608 floats
        for (int idx = tid; idx < 9 * 8 * 64; idx += 256) {
            int ocl = idx & 63;
            int icl = (idx >> 6) & 7;
            int k   = idx >> 9;                 // ky*3+kx
            s_w[k][icl][ocl] = wgt[(k * CIN + ic0 + icl) * COUT + ocl];
        }
        // input chunk: 3 rows x 8 ic x 66 x-positions
        for (int idx = tid; idx < 3 * 8 * 66; idx += 256) {
            int xx  = idx % 66;                 // rel = xx - 1
            int t2  = idx / 66;
            int icl = t2 & 7;
            int ky  = t2 >> 3;
            int gy  = y + ky - 1;
            int gx  = xbase + xx - 1;
            float v = 0.f;
            if ((unsigned)gy < (unsigned)HH && (unsigned)gx < (unsigned)WW)
                v = in[((bb * HH + gy) * WW + gx) * CIN + ic0 + icl];
            s_in[ky][icl][xx + 3] = v;
        }
        __syncthreads();

        for (int icl = 0; icl < 8; ++icl) {
#pragma unroll
            for (int ky = 0; ky < 3; ++ky) {
                float r[24];
                const float4* rowp = (const float4*)&s_in[ky][icl][px0];
#pragma unroll
                for (int q = 0; q < 6; ++q) {
                    float4 t4 = rowp[q];
                    r[4 * q + 0] = t4.x; r[4 * q + 1] = t4.y;
                    r[4 * q + 2] = t4.z; r[4 * q + 3] = t4.w;
                }
#pragma unroll
                for (int kx = 0; kx < 3; ++kx) {
                    float wv = s_w[ky * 3 + kx][icl][oc];
#pragma unroll
                    for (int p = 0; p < 16; ++p)
                        acc[p] = fmaf(r[p + kx + 3], wv, acc[p]);
                }
            }
        }
    }

    // folded BN: y = conv*sc + sh
    float sc = gam[oc] * rsqrtf(var[oc] + EPS);
    float sh = (bias[oc] - mu[oc]) * sc + bet[oc];
    float* op = &out[((bb * HH + y) * WW + xbase + px0) * COUT + oc];
#pragma unroll
    for (int p = 0; p < 16; ++p) {
        float v = acc[p] * sc + sh;
        if (do_relu) v = fmaxf(v, 0.f);
        op[p * COUT] = v;
    }
}

// ---------------------------------------------------------------------------
// Softmax over NB=4 (channel = cc*4 + f) + mask (> 1e-5), in place.
// One thread per (pixel, cc) -> one float4.
// ---------------------------------------------------------------------------
__global__ void softmax_mask_kernel(float* __restrict__ bf, int n4)
{
    int idx = blockIdx.x * blockDim.x + threadIdx.x;
    if (idx >= n4) return;
    float4 v = ((const float4*)bf)[idx];
    float mx = fmaxf(fmaxf(v.x, v.y), fmaxf(v.z, v.w));
    float ex = __expf(v.x - mx);
    float ey = __expf(v.y - mx);
    float ez = __expf(v.z - mx);
    float ew = __expf(v.w - mx);
    float inv = 1.f / (ex + ey + ez + ew);
    ex *= inv; ey *= inv; ez *= inv; ew *= inv;
    float4 o;
    o.x = ex > 1e-5f ? ex : 0.f;
    o.y = ey > 1e-5f ? ey : 0.f;
    o.z = ez > 1e-5f ? ez : 0.f;
    o.w = ew > 1e-5f ? ew : 0.f;
    ((float4*)bf)[idx] = o;
}

// ---------------------------------------------------------------------------
// Per-patch ratio = divide_no_nan(sum(pet*b), sum(b)) for each (cc, f).
// Patch (n,m) covers global pixels (n*4-2+xp, m*4-2+yp), xp,yp in [0,8),
// zero outside the image (SAME extract_patches padding = 2 each side).
// Block: 256 threads = 16 patches x 16 cc; f handled as float4.
// ---------------------------------------------------------------------------
__global__ __launch_bounds__(256) void ratio_kernel(
    const float* __restrict__ bf, const float* __restrict__ pet,
    float* __restrict__ ratio)
{
    int tid = threadIdx.x;
    int pid = blockIdx.x * 16 + (tid >> 4);   // 0 .. B*64*64-1
    int cc  = tid & 15;
    int b   = pid >> 12;
    int nm  = pid & 4095;
    int n   = nm >> 6;
    int m   = nm & 63;

    float4 dn = make_float4(0.f, 0.f, 0.f, 0.f);
    float4 kp = make_float4(0.f, 0.f, 0.f, 0.f);
    int gx0 = n * 4 - 2, gy0 = m * 4 - 2;

    for (int xp = 0; xp < 8; ++xp) {
        int gx = gx0 + xp;
        if ((unsigned)gx >= (unsigned)HH) continue;
        for (int yp = 0; yp < 8; ++yp) {
            int gy = gy0 + yp;
            if ((unsigned)gy >= (unsigned)WW) continue;
            int pix = (b * HH + gx) * WW + gy;
            float4 bv = *(const float4*)&bf[pix * COUT + cc * 4];
            float  pv = pet[pix * CC + cc];
            dn.x += bv.x; dn.y += bv.y; dn.z += bv.z; dn.w += bv.w;
            kp.x = fmaf(pv, bv.x, kp.x);
            kp.y = fmaf(pv, bv.y, kp.y);
            kp.z = fmaf(pv, bv.z, kp.z);
            kp.w = fmaf(pv, bv.w, kp.w);
        }
    }
    float4 r;
    r.x = dn.x != 0.f ? kp.x / dn.x : 0.f;
    r.y = dn.y != 0.f ? kp.y / dn.y : 0.f;
    r.z = dn.z != 0.f ? kp.z / dn.z : 0.f;
    r.w = dn.w != 0.f ? kp.w / dn.w : 0.f;
    ((float4*)ratio)[pid * 16 + cc] = r;
}

// ---------------------------------------------------------------------------
// Final gather: deinterleave + roll + mean collapses to
// out[b,X,Y,cc] = 1/4 * sum_{i,j} sum_f ratio[b,n,m,cc,f] * bf[b,gx,gy,cc,f]
// with X' = (X - rx[i]) mod 256 (rx = {-2,+2}), n = (X'>>3)*2 + i,
// gx = X' + 4i - 2 (zero outside image). Same for Y/j.
// ---------------------------------------------------------------------------
__global__ void out_kernel(const float* __restrict__ bf,
                           const float* __restrict__ ratio,
                           float* __restrict__ out, int ntot)
{
    int idx = blockIdx.x * blockDim.x + threadIdx.x;
    if (idx >= ntot) return;
    int cc  = idx & 15;
    int pix = idx >> 4;
    int Y = pix & 255;
    int t = pix >> 8;
    int X = t & 255;
    int b = t >> 8;

    float s = 0.f;
#pragma unroll
    for (int j = 0; j < 2; ++j) {
        int Yp = (Y - (j ? 2 : -2)) & 255;
        int m  = (Yp >> 3) * 2 + j;
        int gy = Yp + 4 * j - 2;
#pragma unroll
        for (int i = 0; i < 2; ++i) {
            int Xp = (X - (i ? 2 : -2)) & 255;
            int n  = (Xp >> 3) * 2 + i;
            int gx = Xp + 4 * i - 2;
            if ((unsigned)gx < (unsigned)HH && (unsigned)gy < (unsigned)WW) {
                int pp = (b * HH + gx) * WW + gy;
                float4 bv = *(const float4*)&bf[pp * COUT + cc * 4];
                float4 rv = *(const float4*)&ratio[(((b * SN + n) * SN + m) * CC + cc) * 4];
                s += bv.x * rv.x + bv.y * rv.y + bv.z * rv.z + bv.w * rv.w;
            }
        }
    }
    out[idx] = s * 0.25f;
}

// ---------------------------------------------------------------------------
extern "C" void kernel_launch(void* const* d_in, const int* in_sizes, int n_in,
                              void* d_out, int out_size)
{
    const float* mr  = (const float*)d_in[0];
    const float* pet = (const float*)d_in[1];
    const float* W1  = (const float*)d_in[2];
    const float* b1  = (const float*)d_in[3];
    const float* g1  = (const float*)d_in[4];
    const float* be1 = (const float*)d_in[5];
    const float* mu1 = (const float*)d_in[6];
    const float* v1  = (const float*)d_in[7];
    const float* W2  = (const float*)d_in[8];
    const float* b2  = (const float*)d_in[9];
    const float* g2  = (const float*)d_in[10];
    const float* be2 = (const float*)d_in[11];
    const float* mu2 = (const float*)d_in[12];
    const float* v2  = (const float*)d_in[13];
    float* outp = (float*)d_out;

    float *x1p, *bfp, *ratp;
    cudaGetSymbolAddress((void**)&x1p, g_x1);
    cudaGetSymbolAddress((void**)&bfp, g_bf);
    cudaGetSymbolAddress((void**)&ratp, g_ratio);

    dim3 cgrid(WW / 64, HH, BB);
    conv3x3_bn<CC><<<cgrid, 256>>>(mr, W1, b1, g1, be1, mu1, v1, x1p, 1);
    conv3x3_bn<COUT><<<cgrid, 256>>>(x1p, W2, b2, g2, be2, mu2, v2, bfp, 0);

    int n4 = BB * HH * WW * CC;           // number of float4 groups (pixel, cc)
    softmax_mask_kernel<<<(n4 + 255) / 256, 256>>>(bfp, n4);

    ratio_kernel<<<(BB * SN * SN) / 16, 256>>>(bfp, pet, ratp);

    int ntot = BB * HH * WW * CC;
    out_kernel<<<(ntot + 255) / 256, 256>>>(bfp, ratp, outp, ntot);
}

// round 4
// speedup vs baseline: 2.9633x; 2.9633x over previous
#include <cuda_runtime.h>
#include <cuda_bf16.h>
#include <cstdint>

// Problem constants
#define BB 3
#define HH 256
#define WW 256
#define CC 16
#define NB 4
#define COUT 64
#define SN 64
#define EPS 1e-3f

// Scratch (__device__ globals: allocation-free rule)
__device__ float g_x1[BB * HH * WW * COUT];      // conv1 output (BN+ReLU, fp32)
__device__ float g_bf[BB * HH * WW * COUT];      // conv2 out -> softmax/mask in place
__device__ float g_ratio[BB * SN * SN * CC * NB];
__device__ float g_B1[9 * 64 * 16];              // W1 transposed [t][oc][ic], tf32-rounded
__device__ float g_B2[9 * 64 * 64];              // W2 transposed [t][oc][ic], tf32-rounded

__device__ __forceinline__ uint32_t f2tf32(float f) {
    uint32_t r; asm("cvt.rna.tf32.f32 %0, %1;" : "=r"(r) : "f"(f)); return r;
}

__device__ __forceinline__ void mma_tf32(float& c0, float& c1, float& c2, float& c3,
                                         uint32_t a0, uint32_t a1, uint32_t a2, uint32_t a3,
                                         uint32_t b0, uint32_t b1) {
    asm volatile(
        "mma.sync.aligned.m16n8k8.row.col.f32.tf32.tf32.f32 "
        "{%0,%1,%2,%3}, {%4,%5,%6,%7}, {%8,%9}, {%0,%1,%2,%3};\n"
        : "+f"(c0), "+f"(c1), "+f"(c2), "+f"(c3)
        : "r"(a0), "r"(a1), "r"(a2), "r"(a3), "r"(b0), "r"(b1));
}

// ---------------------------------------------------------------------------
// Weight prep: W [3,3,CIN,64] (HWIO) -> B [9][64][CIN] tf32-rounded fp32
// ---------------------------------------------------------------------------
__global__ void wprep_kernel(const float* __restrict__ W1, const float* __restrict__ W2,
                             float* __restrict__ B1, float* __restrict__ B2)
{
    int i = blockIdx.x * blockDim.x + threadIdx.x;
    if (i < 9 * 64 * 16) {
        int ic = i & 15, oc = (i >> 4) & 63, t = i >> 10;
        uint32_t v = f2tf32(W1[(t * 16 + ic) * 64 + oc]);
        B1[(t * 64 + oc) * 16 + ic] = __uint_as_float(v);
    }
    if (i < 9 * 64 * 64) {
        int ic = i & 63, oc = (i >> 6) & 63, t = i >> 12;
        uint32_t v = f2tf32(W2[(t * 64 + ic) * 64 + oc]);
        B2[(t * 64 + oc) * 64 + ic] = __uint_as_float(v);
    }
}

// ---------------------------------------------------------------------------
// Implicit-GEMM 3x3 SAME conv via mma.sync tf32 + folded BN (+optional ReLU).
// CTA = one image row: 256 pixels x 64 oc. 4 warps; warp w owns pixels
// [64w, 64w+64) (4 m16 tiles) x all 64 oc (8 n8 tiles) -> 32 MMAs per k8.
// Per (ky, 16-ic chunk): stage A [258 px x 16 ic] and B [3 taps x 64 oc x 16 ic]
// in padded smem (stride 20 floats -> conflict-free frag LDS), then
// 3 kx-taps x 2 k8-groups of MMAs; kx realized as +kx row offset into A.
// ---------------------------------------------------------------------------
#define ASTR 20
template <int CIN, int DO_RELU>
__global__ __launch_bounds__(128) void conv_mma(
    const float* __restrict__ in, const float* __restrict__ Bw,
    const float* __restrict__ bias, const float* __restrict__ gam,
    const float* __restrict__ bet, const float* __restrict__ mu,
    const float* __restrict__ var, float* __restrict__ out)
{
    __shared__ __align__(16) float s_a[258 * ASTR];       // 20640 B
    __shared__ __align__(16) float s_b[3 * 64 * ASTR];    // 15360 B
    __shared__ float s_sc[64], s_sh[64];

    const int tid  = threadIdx.x;
    const int lane = tid & 31;
    const int warp = tid >> 5;
    const int lg   = lane >> 2;     // group id (row within tile)
    const int lt   = lane & 3;      // thread-in-group (col)
    const int wp0  = warp * 64;     // warp pixel base

    const int y  = blockIdx.x;
    const int bb = blockIdx.y;

    if (tid < 64) {
        float sc = gam[tid] * rsqrtf(var[tid] + EPS);
        s_sc[tid] = sc;
        s_sh[tid] = (bias[tid] - mu[tid]) * sc + bet[tid];
    }

    float acc[4][8][4];
#pragma unroll
    for (int mt = 0; mt < 4; ++mt)
#pragma unroll
        for (int n = 0; n < 8; ++n)
#pragma unroll
            for (int c = 0; c < 4; ++c) acc[mt][n][c] = 0.f;

    for (int ky = 0; ky < 3; ++ky) {
        const int gy = y + ky - 1;
        const bool row_ok = (unsigned)gy < (unsigned)HH;
        const float* rowp = in + ((size_t)(bb * HH + gy) * WW) * CIN;

        for (int ic0 = 0; ic0 < CIN; ic0 += 16) {
            __syncthreads();
            // ---- stage A: 258 rows (gx = p-1) x 16 ic, tf32-rounded
            for (int idx = tid; idx < 258 * 4; idx += 128) {
                int c4 = idx & 3;
                int p  = idx >> 2;
                int gx = p - 1;
                uint4 v = make_uint4(0u, 0u, 0u, 0u);
                if (row_ok && (unsigned)gx < (unsigned)WW) {
                    float4 f = *(const float4*)(rowp + gx * CIN + ic0 + c4 * 4);
                    v.x = f2tf32(f.x); v.y = f2tf32(f.y);
                    v.z = f2tf32(f.z); v.w = f2tf32(f.w);
                }
                *(uint4*)&s_a[p * ASTR + c4 * 4] = v;
            }
            // ---- stage B: 3 taps x 64 oc x 16 ic (already tf32-rounded)
            for (int idx = tid; idx < 3 * 64 * 4; idx += 128) {
                int c4  = idx & 3;
                int oc  = (idx >> 2) & 63;
                int tap = idx >> 8;
                float4 f = *(const float4*)(Bw + ((ky * 3 + tap) * 64 + oc) * CIN + ic0 + c4 * 4);
                *(float4*)&s_b[(tap * 64 + oc) * ASTR + c4 * 4] = f;
            }
            __syncthreads();

#pragma unroll
            for (int kx = 0; kx < 3; ++kx) {
#pragma unroll
                for (int g = 0; g < 2; ++g) {
                    const int icw = g * 8 + lt;
                    // B fragments: 8 n-tiles
                    uint32_t b0[8], b1[8];
#pragma unroll
                    for (int n = 0; n < 8; ++n) {
                        const float* bp = &s_b[(kx * 64 + n * 8 + lg) * ASTR + icw];
                        b0[n] = __float_as_uint(bp[0]);
                        b1[n] = __float_as_uint(bp[4]);
                    }
#pragma unroll
                    for (int mt = 0; mt < 4; ++mt) {
                        const int r0 = wp0 + mt * 16 + kx + lg;
                        const float* ap0 = &s_a[r0 * ASTR + icw];
                        const float* ap1 = ap0 + 8 * ASTR;
                        uint32_t a0 = __float_as_uint(ap0[0]);
                        uint32_t a1 = __float_as_uint(ap1[0]);
                        uint32_t a2 = __float_as_uint(ap0[4]);
                        uint32_t a3 = __float_as_uint(ap1[4]);
#pragma unroll
                        for (int n = 0; n < 8; ++n)
                            mma_tf32(acc[mt][n][0], acc[mt][n][1], acc[mt][n][2], acc[mt][n][3],
                                     a0, a1, a2, a3, b0[n], b1[n]);
                    }
                }
            }
        }
    }

    // ---- epilogue: BN (+ReLU), store fp32 NHWC
    float* ob = out + ((size_t)(bb * HH + y) * WW) * COUT;
#pragma unroll
    for (int mt = 0; mt < 4; ++mt) {
        int prow = wp0 + mt * 16 + lg;
#pragma unroll
        for (int n = 0; n < 8; ++n) {
            int col = n * 8 + lt * 2;
            float sc0 = s_sc[col], sc1 = s_sc[col + 1];
            float sh0 = s_sh[col], sh1 = s_sh[col + 1];
            float v0 = acc[mt][n][0] * sc0 + sh0;
            float v1 = acc[mt][n][1] * sc1 + sh1;
            float v2 = acc[mt][n][2] * sc0 + sh0;
            float v3 = acc[mt][n][3] * sc1 + sh1;
            if (DO_RELU) {
                v0 = fmaxf(v0, 0.f); v1 = fmaxf(v1, 0.f);
                v2 = fmaxf(v2, 0.f); v3 = fmaxf(v3, 0.f);
            }
            *(float2*)(ob + (size_t)prow * COUT + col)       = make_float2(v0, v1);
            *(float2*)(ob + (size_t)(prow + 8) * COUT + col) = make_float2(v2, v3);
        }
    }
}

// ---------------------------------------------------------------------------
// Softmax over NB=4 + mask, in place.
// ---------------------------------------------------------------------------
__global__ void softmax_mask_kernel(float* __restrict__ bf, int n4)
{
    int idx = blockIdx.x * blockDim.x + threadIdx.x;
    if (idx >= n4) return;
    float4 v = ((const float4*)bf)[idx];
    float mx = fmaxf(fmaxf(v.x, v.y), fmaxf(v.z, v.w));
    float ex = __expf(v.x - mx);
    float ey = __expf(v.y - mx);
    float ez = __expf(v.z - mx);
    float ew = __expf(v.w - mx);
    float inv = 1.f / (ex + ey + ez + ew);
    ex *= inv; ey *= inv; ez *= inv; ew *= inv;
    float4 o;
    o.x = ex > 1e-5f ? ex : 0.f;
    o.y = ey > 1e-5f ? ey : 0.f;
    o.z = ez > 1e-5f ? ez : 0.f;
    o.w = ew > 1e-5f ? ew : 0.f;
    ((float4*)bf)[idx] = o;
}

// ---------------------------------------------------------------------------
// Per-patch ratio = divide_no_nan(sum(pet*b), sum(b)) per (cc, f).
// ---------------------------------------------------------------------------
__global__ __launch_bounds__(256) void ratio_kernel(
    const float* __restrict__ bf, const float* __restrict__ pet,
    float* __restrict__ ratio)
{
    int tid = threadIdx.x;
    int pid = blockIdx.x * 16 + (tid >> 4);
    int cc  = tid & 15;
    int b   = pid >> 12;
    int nm  = pid & 4095;
    int n   = nm >> 6;
    int m   = nm & 63;

    float4 dn = make_float4(0.f, 0.f, 0.f, 0.f);
    float4 kp = make_float4(0.f, 0.f, 0.f, 0.f);
    int gx0 = n * 4 - 2, gy0 = m * 4 - 2;

    for (int xp = 0; xp < 8; ++xp) {
        int gx = gx0 + xp;
        if ((unsigned)gx >= (unsigned)HH) continue;
        for (int yp = 0; yp < 8; ++yp) {
            int gy = gy0 + yp;
            if ((unsigned)gy >= (unsigned)WW) continue;
            int pix = (b * HH + gx) * WW + gy;
            float4 bv = *(const float4*)&bf[pix * COUT + cc * 4];
            float  pv = pet[pix * CC + cc];
            dn.x += bv.x; dn.y += bv.y; dn.z += bv.z; dn.w += bv.w;
            kp.x = fmaf(pv, bv.x, kp.x);
            kp.y = fmaf(pv, bv.y, kp.y);
            kp.z = fmaf(pv, bv.z, kp.z);
            kp.w = fmaf(pv, bv.w, kp.w);
        }
    }
    float4 r;
    r.x = dn.x != 0.f ? kp.x / dn.x : 0.f;
    r.y = dn.y != 0.f ? kp.y / dn.y : 0.f;
    r.z = dn.z != 0.f ? kp.z / dn.z : 0.f;
    r.w = dn.w != 0.f ? kp.w / dn.w : 0.f;
    ((float4*)ratio)[pid * 16 + cc] = r;
}

// ---------------------------------------------------------------------------
// Final gather: deinterleave + roll + mean collapsed form.
// ---------------------------------------------------------------------------
__global__ void out_kernel(const float* __restrict__ bf,
                           const float* __restrict__ ratio,
                           float* __restrict__ out, int ntot)
{
    int idx = blockIdx.x * blockDim.x + threadIdx.x;
    if (idx >= ntot) return;
    int cc  = idx & 15;
    int pix = idx >> 4;
    int Y = pix & 255;
    int t = pix >> 8;
    int X = t & 255;
    int b = t >> 8;

    float s = 0.f;
#pragma unroll
    for (int j = 0; j < 2; ++j) {
        int Yp = (Y - (j ? 2 : -2)) & 255;
        int m  = (Yp >> 3) * 2 + j;
        int gy = Yp + 4 * j - 2;
#pragma unroll
        for (int i = 0; i < 2; ++i) {
            int Xp = (X - (i ? 2 : -2)) & 255;
            int n  = (Xp >> 3) * 2 + i;
            int gx = Xp + 4 * i - 2;
            if ((unsigned)gx < (unsigned)HH && (unsigned)gy < (unsigned)WW) {
                int pp = (b * HH + gx) * WW + gy;
                float4 bv = *(const float4*)&bf[pp * COUT + cc * 4];
                float4 rv = *(const float4*)&ratio[(((b * SN + n) * SN + m) * CC + cc) * 4];
                s += bv.x * rv.x + bv.y * rv.y + bv.z * rv.z + bv.w * rv.w;
            }
        }
    }
    out[idx] = s * 0.25f;
}

// ---------------------------------------------------------------------------
extern "C" void kernel_launch(void* const* d_in, const int* in_sizes, int n_in,
                              void* d_out, int out_size)
{
    const float* mr  = (const float*)d_in[0];
    const float* pet = (const float*)d_in[1];
    const float* W1  = (const float*)d_in[2];
    const float* b1  = (const float*)d_in[3];
    const float* g1  = (const float*)d_in[4];
    const float* be1 = (const float*)d_in[5];
    const float* mu1 = (const float*)d_in[6];
    const float* v1  = (const float*)d_in[7];
    const float* W2  = (const float*)d_in[8];
    const float* b2  = (const float*)d_in[9];
    const float* g2  = (const float*)d_in[10];
    const float* be2 = (const float*)d_in[11];
    const float* mu2 = (const float*)d_in[12];
    const float* v2  = (const float*)d_in[13];
    float* outp = (float*)d_out;

    float *x1p, *bfp, *ratp, *B1p, *B2p;
    cudaGetSymbolAddress((void**)&x1p, g_x1);
    cudaGetSymbolAddress((void**)&bfp, g_bf);
    cudaGetSymbolAddress((void**)&ratp, g_ratio);
    cudaGetSymbolAddress((void**)&B1p, g_B1);
    cudaGetSymbolAddress((void**)&B2p, g_B2);

    wprep_kernel<<<(9 * 64 * 64 + 255) / 256, 256>>>(W1, W2, B1p, B2p);

    dim3 cgrid(HH, BB);
    conv_mma<16, 1><<<cgrid, 128>>>(mr, B1p, b1, g1, be1, mu1, v1, x1p);
    conv_mma<64, 0><<<cgrid, 128>>>(x1p, B2p, b2, g2, be2, mu2, v2, bfp);

    int n4 = BB * HH * WW * CC;
    softmax_mask_kernel<<<(n4 + 255) / 256, 256>>>(bfp, n4);

    ratio_kernel<<<(BB * SN * SN) / 16, 256>>>(bfp, pet, ratp);

    int ntot = BB * HH * WW * CC;
    out_kernel<<<(ntot + 255) / 256, 256>>>(bfp, ratp, outp, ntot);
}